// round 1
// baseline (speedup 1.0000x reference)
#include <cuda_runtime.h>
#include <cuda_bf16.h>
#include <cstddef>

// Problem constants (fixed by the reference):
//   B=64, NTH=56, NTW=56  -> T = 200704 tiles
//   M = 8 slots/tile, DF = 8 flux fields, D = 2 + DF + 1 = 11 output fields
static constexpr float FAR_SENTINEL = 100.0f;
static constexpr float FLT_BIG = 3.402823466e38f;

__global__ __launch_bounds__(256) void match_scatter_kernel(
    const float* __restrict__ est_locs,    // [T, 8, 2]
    const float* __restrict__ true_locs,   // [T, 8, 2]
    const float* __restrict__ true_fluxes, // [T, 8, 8]
    const int*   __restrict__ est_ns,      // [T]
    const int*   __restrict__ true_ns,     // [T]
    float*       __restrict__ out,         // [T, 8, 11]
    int T)
{
    const int t = blockIdx.x * blockDim.x + threadIdx.x;
    if (t >= T) return;

    const int n_e = est_ns[t];
    const int n_t = true_ns[t];

    // ---- load locs (vectorized, 4x float4 each) ----
    float elx[8], ely[8], tlx[8], tly[8];
    {
        const float4* ep = reinterpret_cast<const float4*>(est_locs)  + (size_t)t * 4;
        const float4* tp = reinterpret_cast<const float4*>(true_locs) + (size_t)t * 4;
        #pragma unroll
        for (int i = 0; i < 4; ++i) {
            float4 e  = ep[i];
            float4 tr = tp[i];
            elx[2*i]   = e.x;  ely[2*i]   = e.y;
            elx[2*i+1] = e.z;  ely[2*i+1] = e.w;
            tlx[2*i]   = tr.x; tly[2*i]   = tr.y;
            tlx[2*i+1] = tr.z; tly[2*i+1] = tr.w;
        }
    }

    // ---- 8x8 distance pass: match1 (argmin over est rows, per true col)
    //                         match2 (argmin over true cols, per est row) ----
    float colmin[8];
    int   colarg[8];     // match1[s]
    int   match2[8];
    #pragma unroll
    for (int s = 0; s < 8; ++s) { colmin[s] = FLT_BIG; colarg[s] = 0; }

    #pragma unroll
    for (int i = 0; i < 8; ++i) {
        const float ex = (i < n_e) ? elx[i] : FAR_SENTINEL;
        const float ey = (i < n_e) ? ely[i] : FAR_SENTINEL;
        float rmin = FLT_BIG;
        int   rarg = 0;
        #pragma unroll
        for (int s = 0; s < 8; ++s) {
            const float tx = (s < n_t) ? tlx[s] : FAR_SENTINEL;
            const float ty = (s < n_t) ? tly[s] : FAR_SENTINEL;
            const float dx = __fadd_rn(ex, -tx);
            const float dy = __fadd_rn(ey, -ty);
            // unfused to match jnp's dx*dx + dy*dy exactly (tie-break safety)
            const float d  = sqrtf(__fadd_rn(__fmul_rn(dx, dx), __fmul_rn(dy, dy)));
            if (d < rmin)      { rmin = d;      rarg = i == i ? s : s; }
            if (d < colmin[s]) { colmin[s] = d; colarg[s] = i; }
        }
        match2[i] = rarg;
    }

    // ---- one-to-one condition per slot s:
    //   match1[match2[s]] == s  &&  match1[s] < n_e  &&  match2[s] < n_t
    // expanded with constant indexing only (keeps everything in registers) ----
    bool ok[8];
    #pragma unroll
    for (int s = 0; s < 8; ++s) {
        const int m2 = match2[s];
        bool eq = false;
        #pragma unroll
        for (int j = 0; j < 8; ++j)
            eq |= (m2 == j) & (colarg[j] == s);
        ok[s] = eq && (colarg[s] < n_e) && (m2 < n_t);
    }

    // ---- assemble output tile in a register buffer, then 22x float4 store ----
    float outbuf[88];
    #pragma unroll
    for (int k = 0; k < 88; ++k) outbuf[k] = 0.0f;

    const float4* fp = reinterpret_cast<const float4*>(true_fluxes) + (size_t)t * 16;
    const float*  tl_base = true_locs + (size_t)t * 16;

    #pragma unroll
    for (int p = 0; p < 8; ++p) {
        // scatter semantics: target[match1[s]] = padded_true[match2[s]] for matched s,
        // sequential s order => last-write-wins (matches sequential scatter).
        int sp = -1;
        #pragma unroll
        for (int s = 0; s < 8; ++s)
            if (ok[s] && (colarg[s] == p)) sp = match2[s];

        if (sp >= 0) {
            // raw (unmasked) true locs; guaranteed L1 hit (line loaded above)
            outbuf[p*11 + 0] = tl_base[sp*2 + 0];
            outbuf[p*11 + 1] = tl_base[sp*2 + 1];
            const float4 f0 = fp[sp*2 + 0];
            const float4 f1 = fp[sp*2 + 1];
            outbuf[p*11 + 2] = f0.x; outbuf[p*11 + 3] = f0.y;
            outbuf[p*11 + 4] = f0.z; outbuf[p*11 + 5] = f0.w;
            outbuf[p*11 + 6] = f1.x; outbuf[p*11 + 7] = f1.y;
            outbuf[p*11 + 8] = f1.z; outbuf[p*11 + 9] = f1.w;
            // true_on indicator: matched implies sp < n_t, so always 1
            outbuf[p*11 + 10] = 1.0f;
        }
    }

    float4* op = reinterpret_cast<float4*>(out) + (size_t)t * 22;
    #pragma unroll
    for (int q = 0; q < 22; ++q)
        op[q] = make_float4(outbuf[4*q + 0], outbuf[4*q + 1],
                            outbuf[4*q + 2], outbuf[4*q + 3]);
}

extern "C" void kernel_launch(void* const* d_in, const int* in_sizes, int n_in,
                              void* d_out, int out_size)
{
    const float* est_locs    = (const float*)d_in[0];
    const float* true_locs   = (const float*)d_in[1];
    const float* true_fluxes = (const float*)d_in[2];
    const int*   est_ns      = (const int*)d_in[3];
    const int*   true_ns     = (const int*)d_in[4];
    float*       out         = (float*)d_out;

    const int T = in_sizes[3];   // est_n_sources element count == number of tiles

    const int threads = 256;
    const int blocks  = (T + threads - 1) / threads;
    match_scatter_kernel<<<blocks, threads>>>(est_locs, true_locs, true_fluxes,
                                              est_ns, true_ns, out, T);
}